// round 2
// baseline (speedup 1.0000x reference)
#include <cuda_runtime.h>
#include <math.h>

// Problem dims (fixed by the dataset)
#define S_LEN 128
#define BATCH 512
#define IDIM  512
#define HDIM  256
#define ODIM  256
#define NROWS (S_LEN*BATCH)   // 65536

// ---------------- scratch (static device arrays; no allocation) ----------------
__device__ float g_WihT[IDIM*HDIM];              // [k][h] transposed W_ih (first 512 cols)
__device__ float g_WhhT[HDIM*HDIM];              // [k][h]
__device__ float g_WoutT[HDIM*ODIM];             // [k][o]
__device__ float g_flagv[HDIM];                  // W_ih[:,512]
__device__ float g_bias1[HDIM];                  // b_ih + b_hh
__device__ float g_pre [(size_t)NROWS*HDIM];     // X @ WihT + bias1
__device__ float g_sacc[(size_t)NROWS*HDIM];     // sum_n p_n * s_n
__device__ float g_psum[NROWS];                  // sum_n p_n

// ---------------- prep: transposes + bias fold ----------------
__global__ void prep_kernel(const float* __restrict__ W_ih,
                            const float* __restrict__ b_ih,
                            const float* __restrict__ b_hh,
                            const float* __restrict__ W_hh,
                            const float* __restrict__ W_out)
{
    int idx = blockIdx.x * blockDim.x + threadIdx.x;
    if (idx < IDIM*HDIM) {
        int k = idx / HDIM, h = idx % HDIM;
        g_WihT[idx] = W_ih[h*(IDIM+1) + k];
    }
    if (idx < HDIM*HDIM) {
        int k = idx / HDIM, h = idx % HDIM;
        g_WhhT[idx]  = W_hh [h*HDIM + k];
        g_WoutT[idx] = W_out[h*HDIM + k];
    }
    if (idx < HDIM) {
        g_flagv[idx] = W_ih[idx*(IDIM+1) + IDIM];
        g_bias1[idx] = b_ih[idx] + b_hh[idx];
    }
}

// ---------------- generic fp32 SGEMM: C = A@B + biasN + rowscale*bias2 ----------------
// A: [M,K] row-major, B: [K,N] row-major, C: [M,N].
// BM=128, BN=64, BK=16, TM=8, TN=4, 256 threads.
#define GBM 128
#define GBN 64
#define GBK 16
#define GTM 8
#define GTN 4

__global__ void __launch_bounds__(256)
sgemm_bias_kernel(const float* __restrict__ A, const float* __restrict__ B,
                  float* __restrict__ C,
                  const float* __restrict__ biasN,
                  const float* __restrict__ rowscale,
                  const float* __restrict__ bias2,
                  int M, int N, int K)
{
    __shared__ float As[GBK][GBM];
    __shared__ float Bs[GBK][GBN];

    const int tid = threadIdx.x;
    const int m0 = blockIdx.y * GBM;
    const int n0 = blockIdx.x * GBN;
    const int tx = tid % 16;          // n sub-tile
    const int ty = tid / 16;          // m sub-tile

    // load mapping
    const int aCol4 = (tid % 4) * 4;  // 0,4,8,12 within BK
    const int aRow  = tid / 4;        // 0..63 (two row groups: +0, +64)
    const int bRow  = tid / 16;       // 0..15
    const int bCol4 = (tid % 16) * 4;

    float acc[GTM][GTN];
#pragma unroll
    for (int i = 0; i < GTM; i++)
#pragma unroll
        for (int j = 0; j < GTN; j++) acc[i][j] = 0.f;

    const float* Abase = A + (size_t)m0 * K;

    for (int k0 = 0; k0 < K; k0 += GBK) {
        float4 a0 = *(const float4*)(Abase + (size_t)aRow        * K + k0 + aCol4);
        float4 a1 = *(const float4*)(Abase + (size_t)(aRow + 64) * K + k0 + aCol4);
        float4 b0 = *(const float4*)(B + (size_t)(k0 + bRow) * N + n0 + bCol4);

        As[aCol4+0][aRow] = a0.x; As[aCol4+1][aRow] = a0.y;
        As[aCol4+2][aRow] = a0.z; As[aCol4+3][aRow] = a0.w;
        As[aCol4+0][aRow+64] = a1.x; As[aCol4+1][aRow+64] = a1.y;
        As[aCol4+2][aRow+64] = a1.z; As[aCol4+3][aRow+64] = a1.w;
        *(float4*)&Bs[bRow][bCol4] = b0;
        __syncthreads();

#pragma unroll
        for (int k = 0; k < GBK; k++) {
            float4 av0 = *(const float4*)&As[k][ty*GTM];
            float4 av1 = *(const float4*)&As[k][ty*GTM + 4];
            float4 bv  = *(const float4*)&Bs[k][tx*GTN];
            float a[GTM] = {av0.x, av0.y, av0.z, av0.w, av1.x, av1.y, av1.z, av1.w};
            float b[GTN] = {bv.x, bv.y, bv.z, bv.w};
#pragma unroll
            for (int i = 0; i < GTM; i++)
#pragma unroll
                for (int j = 0; j < GTN; j++)
                    acc[i][j] = fmaf(a[i], b[j], acc[i][j]);
        }
        __syncthreads();
    }

    const int nbase = n0 + tx*GTN;
    float bn[GTN] = {0.f, 0.f, 0.f, 0.f};
    float c2[GTN] = {0.f, 0.f, 0.f, 0.f};
    if (biasN) {
#pragma unroll
        for (int j = 0; j < GTN; j++) bn[j] = biasN[nbase + j];
    }
    if (bias2) {
#pragma unroll
        for (int j = 0; j < GTN; j++) c2[j] = bias2[nbase + j];
    }
#pragma unroll
    for (int i = 0; i < GTM; i++) {
        int row = m0 + ty*GTM + i;
        float rs = rowscale ? rowscale[row] : 0.f;
        float4 o;
        o.x = acc[i][0] + bn[0] + rs*c2[0];
        o.y = acc[i][1] + bn[1] + rs*c2[1];
        o.z = acc[i][2] + bn[2] + rs*c2[2];
        o.w = acc[i][3] + bn[3] + rs*c2[3];
        *(float4*)(C + (size_t)row*N + nbase) = o;
    }
}

// ---------------- persistent ACT recurrence ----------------
// 128 blocks x 256 threads. Block owns 4 batch rows for all 128 timesteps.
// Thread tid owns hidden unit h = tid. W_hh^T: first KS k-slices in smem,
// remaining KR slices register-cached per thread. Early exit when all 4 rows halt.
#define KS 192
#define KR 64
#define RSM (KS*HDIM)     // floats of Wsh
// smem floats: Wsh + s2(1024) + flag(256) + whalt(256) + red(32) + p(4)+hsum(4)+psum(4)+nst(4)+rem(4) + run(4 ints)
#define RECUR_SMEM_FLOATS (RSM + 1024 + 256 + 256 + 32 + 20 + 4)

__global__ void __launch_bounds__(256, 1)
act_recur_kernel(const float* __restrict__ W_halt,
                 const float* __restrict__ b_halt,
                 float* __restrict__ p_out,
                 float* __restrict__ n_out)
{
    extern __shared__ float sh[];
    float*  Wsh      = sh;                    // [KS][HDIM]
    float4* s2       = (float4*)(sh + RSM);   // [HDIM] -> s[k][r0..r3]
    float*  flag_sh  = sh + RSM + 1024;
    float*  whalt_sh = flag_sh + HDIM;
    float*  red      = whalt_sh + HDIM;       // [8 warps][4 rows]
    float*  p_sh     = red + 32;              // [4]
    float*  hsum_s   = p_sh + 4;
    float*  psum_s   = hsum_s + 4;
    float*  nst_s    = psum_s + 4;
    float*  rem_s    = nst_s + 4;
    int*    run_s    = (int*)(rem_s + 4);

    const int tid = threadIdx.x;
    const int rb  = blockIdx.x * 4;           // first batch row of this block

    // stage weights
    for (int i = tid; i < RSM; i += 256) Wsh[i] = g_WhhT[i];
    float wreg[KR];
#pragma unroll
    for (int j = 0; j < KR; j++) wreg[j] = g_WhhT[(KS + j)*HDIM + tid];
    flag_sh[tid]  = g_flagv[tid];
    whalt_sh[tid] = W_halt[tid];
    const float bh = b_halt[0];
    s2[tid] = make_float4(0.f, 0.f, 0.f, 0.f);   // s0 = 0
    __syncthreads();

    const float fl = flag_sh[tid];
    const float wh = whalt_sh[tid];

    for (int t = 0; t < S_LEN; t++) {
        const float* prow = g_pre + ((size_t)(t*BATCH + rb))*HDIM + tid;
        const float pre0 = prow[0];
        const float pre1 = prow[HDIM];
        const float pre2 = prow[2*HDIM];
        const float pre3 = prow[3*HDIM];
        float sa0 = 0.f, sa1 = 0.f, sa2 = 0.f, sa3 = 0.f;

        if (tid < 4) {
            hsum_s[tid] = 0.f; psum_s[tid] = 0.f; nst_s[tid] = 0.f;
            rem_s[tid] = 0.f;  run_s[tid] = 1;
        }
        __syncthreads();

        for (int n = 0; n < 10; n++) {
            float a0 = pre0, a1 = pre1, a2 = pre2, a3 = pre3;
            if (n == 0) { a0 += fl; a1 += fl; a2 += fl; a3 += fl; }

#pragma unroll 8
            for (int k = 0; k < KS; k++) {
                float  w  = Wsh[k*HDIM + tid];
                float4 s4 = s2[k];
                a0 = fmaf(s4.x, w, a0);
                a1 = fmaf(s4.y, w, a1);
                a2 = fmaf(s4.z, w, a2);
                a3 = fmaf(s4.w, w, a3);
            }
#pragma unroll
            for (int j = 0; j < KR; j++) {
                float  w  = wreg[j];
                float4 s4 = s2[KS + j];
                a0 = fmaf(s4.x, w, a0);
                a1 = fmaf(s4.y, w, a1);
                a2 = fmaf(s4.z, w, a2);
                a3 = fmaf(s4.w, w, a3);
            }

            const float sv0 = tanhf(a0);
            const float sv1 = tanhf(a1);
            const float sv2 = tanhf(a2);
            const float sv3 = tanhf(a3);

            // halting dot: block reduction of wh*sv over h
            float q0 = wh*sv0, q1 = wh*sv1, q2 = wh*sv2, q3 = wh*sv3;
#pragma unroll
            for (int o = 16; o > 0; o >>= 1) {
                q0 += __shfl_xor_sync(0xffffffffu, q0, o);
                q1 += __shfl_xor_sync(0xffffffffu, q1, o);
                q2 += __shfl_xor_sync(0xffffffffu, q2, o);
                q3 += __shfl_xor_sync(0xffffffffu, q3, o);
            }
            if ((tid & 31) == 0) {
                int w8 = tid >> 5;
                red[w8*4+0] = q0; red[w8*4+1] = q1;
                red[w8*4+2] = q2; red[w8*4+3] = q3;
            }
            __syncthreads();

            if (tid < 4) {
                float d = 0.f;
#pragma unroll
                for (int w8 = 0; w8 < 8; w8++) d += red[w8*4 + tid];
                float p = 0.f;
                if (run_s[tid]) {
                    float hh = 1.f / (1.f + expf(-(d + bh)));
                    float ns = hsum_s[tid] + hh;
                    bool halted = (ns >= 0.99f);           // 1.0 - EPS
                    p = halted ? (1.f - hsum_s[tid]) : hh;
                    psum_s[tid] += p;
                    nst_s[tid]  += 1.f;
                    if (halted) { rem_s[tid] = 1.f - hsum_s[tid]; run_s[tid] = 0; }
                    hsum_s[tid] = ns;
                }
                p_sh[tid] = p;
            }
            __syncthreads();

            const float p0 = p_sh[0], p1 = p_sh[1], p2 = p_sh[2], p3 = p_sh[3];
            sa0 = fmaf(p0, sv0, sa0);
            sa1 = fmaf(p1, sv1, sa1);
            sa2 = fmaf(p2, sv2, sa2);
            sa3 = fmaf(p3, sv3, sa3);
            s2[tid] = make_float4(sv0, sv1, sv2, sv3);
            const int alive = run_s[0] + run_s[1] + run_s[2] + run_s[3];
            __syncthreads();
            if (alive == 0) break;
        }

        // per-timestep epilogue
        float* so = g_sacc + ((size_t)(t*BATCH + rb))*HDIM + tid;
        so[0]       = sa0;
        so[HDIM]    = sa1;
        so[2*HDIM]  = sa2;
        so[3*HDIM]  = sa3;
        s2[tid] = make_float4(sa0, sa1, sa2, sa3);   // carry = s_acc
        if (tid < 4) {
            int row = t*BATCH + rb + tid;
            g_psum[row] = psum_s[tid];
            p_out[row]  = nst_s[tid] + rem_s[tid];
            n_out[row]  = nst_s[tid];
        }
        __syncthreads();
    }
}

// ---------------- launch ----------------
extern "C" void kernel_launch(void* const* d_in, const int* in_sizes, int n_in,
                              void* d_out, int out_size)
{
    const float* x      = (const float*)d_in[0];
    const float* W_ih   = (const float*)d_in[1];
    const float* b_ih   = (const float*)d_in[2];
    const float* W_hh   = (const float*)d_in[3];
    const float* b_hh   = (const float*)d_in[4];
    const float* W_halt = (const float*)d_in[5];
    const float* b_halt = (const float*)d_in[6];
    const float* W_out  = (const float*)d_in[7];
    const float* b_out  = (const float*)d_in[8];

    float* y     = (float*)d_out;                       // [S,B,O]
    float* p_out = y + (size_t)NROWS * ODIM;            // [S,B]
    float* n_out = p_out + NROWS;                       // [S,B]

    // resolve device scratch symbols
    float *pre_ptr, *sacc_ptr, *wihT_ptr, *woutT_ptr, *bias1_ptr, *psum_ptr;
    cudaGetSymbolAddress((void**)&pre_ptr,   g_pre);
    cudaGetSymbolAddress((void**)&sacc_ptr,  g_sacc);
    cudaGetSymbolAddress((void**)&wihT_ptr,  g_WihT);
    cudaGetSymbolAddress((void**)&woutT_ptr, g_WoutT);
    cudaGetSymbolAddress((void**)&bias1_ptr, g_bias1);
    cudaGetSymbolAddress((void**)&psum_ptr,  g_psum);

    const int recur_smem = RECUR_SMEM_FLOATS * (int)sizeof(float);
    cudaFuncSetAttribute(act_recur_kernel,
                         cudaFuncAttributeMaxDynamicSharedMemorySize, recur_smem);

    // 1) transposes + bias fold
    prep_kernel<<<(IDIM*HDIM + 255)/256, 256>>>(W_ih, b_ih, b_hh, W_hh, W_out);

    // 2) PRE = X @ WihT + (b_ih+b_hh)   [65536,512]@[512,256]
    {
        dim3 grid(HDIM/GBN, NROWS/GBM);
        sgemm_bias_kernel<<<grid, 256>>>(x, wihT_ptr, pre_ptr,
                                         bias1_ptr, nullptr, nullptr,
                                         NROWS, HDIM, IDIM);
    }

    // 3) sequential ACT recurrence (persistent, early-exit)
    act_recur_kernel<<<128, 256, recur_smem>>>(W_halt, b_halt, p_out, n_out);

    // 4) Y = SACC @ WoutT + psum * b_out   [65536,256]@[256,256]
    {
        dim3 grid(ODIM/GBN, NROWS/GBM);
        sgemm_bias_kernel<<<grid, 256>>>(sacc_ptr, woutT_ptr, y,
                                         nullptr, psum_ptr, b_out,
                                         NROWS, ODIM, HDIM);
    }
}

// round 5
// speedup vs baseline: 1.0229x; 1.0229x over previous
#include <cuda_runtime.h>
#include <math.h>

// Problem dims (fixed by the dataset)
#define S_LEN 128
#define BATCH 512
#define IDIM  512
#define HDIM  256
#define ODIM  256
#define NROWS (S_LEN*BATCH)   // 65536

// ---------------- scratch (static device arrays; no allocation) ----------------
__device__ float g_WihT[IDIM*HDIM];              // [k][h] transposed W_ih (first 512 cols)
__device__ float g_WhhT[HDIM*HDIM];              // [k][h]
__device__ float g_WoutT[HDIM*ODIM];             // [k][o]
__device__ float g_flagv[HDIM];                  // W_ih[:,512]
__device__ float g_bias1[HDIM];                  // b_ih + b_hh
__device__ float g_pre [(size_t)NROWS*HDIM];     // X @ WihT + bias1
__device__ float g_sacc[(size_t)NROWS*HDIM];     // sum_n p_n * s_n
__device__ float g_psum[NROWS];                  // sum_n p_n

__device__ __forceinline__ float fast_tanh(float x) {
    float xc = fminf(fmaxf(x, -10.f), 10.f);
    float e  = __expf(2.f * xc);
    return __fdividef(e - 1.f, e + 1.f);
}

// ---------------- prep: transposes + bias fold ----------------
__global__ void prep_kernel(const float* __restrict__ W_ih,
                            const float* __restrict__ b_ih,
                            const float* __restrict__ b_hh,
                            const float* __restrict__ W_hh,
                            const float* __restrict__ W_out)
{
    int idx = blockIdx.x * blockDim.x + threadIdx.x;
    if (idx < IDIM*HDIM) {
        int k = idx / HDIM, h = idx % HDIM;
        g_WihT[idx] = W_ih[h*(IDIM+1) + k];
    }
    if (idx < HDIM*HDIM) {
        int k = idx / HDIM, h = idx % HDIM;
        g_WhhT[idx]  = W_hh [h*HDIM + k];
        g_WoutT[idx] = W_out[h*HDIM + k];
    }
    if (idx < HDIM) {
        g_flagv[idx] = W_ih[idx*(IDIM+1) + IDIM];
        g_bias1[idx] = b_ih[idx] + b_hh[idx];
    }
}

// ---------------- fp32 SGEMM 128x128x16, TM=TN=8 ----------------
// C = A@B (+ biasN) (+ rowscale*bias2).  A:[M,K] B:[K,N] row-major.
#define BM 128
#define BN 128
#define BK 16

__global__ void __launch_bounds__(256)
sgemm_bias_kernel(const float* __restrict__ A, const float* __restrict__ B,
                  float* __restrict__ C,
                  const float* __restrict__ biasN,
                  const float* __restrict__ rowscale,
                  const float* __restrict__ bias2,
                  int M, int N, int K)
{
    __shared__ float As[BK][BM+4];
    __shared__ float Bs[BK][BN];

    const int tid = threadIdx.x;
    const int m0 = blockIdx.y * BM;
    const int n0 = blockIdx.x * BN;
    const int tx = tid & 15;           // n sub-tile 0..15
    const int ty = tid >> 4;           // m sub-tile 0..15

    const int aRow = tid >> 2;         // 0..63 (+64 second group)
    const int aCol = (tid & 3) * 4;    // 0,4,8,12
    const int bRow = tid >> 5;         // 0..7 (+8 second group)
    const int bCol = (tid & 31) * 4;

    float acc[8][8];
#pragma unroll
    for (int i = 0; i < 8; i++)
#pragma unroll
        for (int j = 0; j < 8; j++) acc[i][j] = 0.f;

    for (int k0 = 0; k0 < K; k0 += BK) {
        float4 a0 = *(const float4*)(A + (size_t)(m0 + aRow)      * K + k0 + aCol);
        float4 a1 = *(const float4*)(A + (size_t)(m0 + aRow + 64) * K + k0 + aCol);
        float4 b0 = *(const float4*)(B + (size_t)(k0 + bRow)     * N + n0 + bCol);
        float4 b1 = *(const float4*)(B + (size_t)(k0 + bRow + 8) * N + n0 + bCol);

        As[aCol+0][aRow] = a0.x; As[aCol+1][aRow] = a0.y;
        As[aCol+2][aRow] = a0.z; As[aCol+3][aRow] = a0.w;
        As[aCol+0][aRow+64] = a1.x; As[aCol+1][aRow+64] = a1.y;
        As[aCol+2][aRow+64] = a1.z; As[aCol+3][aRow+64] = a1.w;
        *(float4*)&Bs[bRow][bCol]     = b0;
        *(float4*)&Bs[bRow+8][bCol]   = b1;
        __syncthreads();

#pragma unroll
        for (int k = 0; k < BK; k++) {
            float4 av0 = *(const float4*)&As[k][ty*8];
            float4 av1 = *(const float4*)&As[k][ty*8 + 4];
            float4 bv0 = *(const float4*)&Bs[k][tx*8];
            float4 bv1 = *(const float4*)&Bs[k][tx*8 + 4];
            float av[8] = {av0.x, av0.y, av0.z, av0.w, av1.x, av1.y, av1.z, av1.w};
            float bv[8] = {bv0.x, bv0.y, bv0.z, bv0.w, bv1.x, bv1.y, bv1.z, bv1.w};
#pragma unroll
            for (int i = 0; i < 8; i++)
#pragma unroll
                for (int j = 0; j < 8; j++)
                    acc[i][j] = fmaf(av[i], bv[j], acc[i][j]);
        }
        __syncthreads();
    }

    const int nbase = n0 + tx*8;
    float bn[8] = {0,0,0,0,0,0,0,0};
    float c2[8] = {0,0,0,0,0,0,0,0};
    if (biasN) {
#pragma unroll
        for (int j = 0; j < 8; j++) bn[j] = biasN[nbase + j];
    }
    if (bias2) {
#pragma unroll
        for (int j = 0; j < 8; j++) c2[j] = bias2[nbase + j];
    }
#pragma unroll
    for (int i = 0; i < 8; i++) {
        int row = m0 + ty*8 + i;
        float rs = rowscale ? rowscale[row] : 0.f;
        float4 o0, o1;
        o0.x = acc[i][0] + bn[0] + rs*c2[0];  o0.y = acc[i][1] + bn[1] + rs*c2[1];
        o0.z = acc[i][2] + bn[2] + rs*c2[2];  o0.w = acc[i][3] + bn[3] + rs*c2[3];
        o1.x = acc[i][4] + bn[4] + rs*c2[4];  o1.y = acc[i][5] + bn[5] + rs*c2[5];
        o1.z = acc[i][6] + bn[6] + rs*c2[6];  o1.w = acc[i][7] + bn[7] + rs*c2[7];
        *(float4*)(C + (size_t)row*N + nbase)     = o0;
        *(float4*)(C + (size_t)row*N + nbase + 4) = o1;
    }
}

// ---------------- persistent ACT recurrence (scalar FMA, double-buffered s) ----------------
// 128 blocks x 256 threads; block owns 4 batch rows for all 128 timesteps.
// Thread tid owns hidden column h = tid. W_hh^T: KS k-slices in smem stored as
// k-pairs (one float2 per thread per pair), KR slices register-cached.
#define KS 192
#define KR 64
#define KSP (KS/2)
#define WSH_FLOATS (KS*HDIM)
// floats: Wsh + 2 s-buffers (2*1024) + flag(256) + whalt(256) + red(32) + 5*4 + run(4)
#define RECUR_SMEM_FLOATS (WSH_FLOATS + 2048 + 256 + 256 + 32 + 20 + 4)

__global__ void __launch_bounds__(256, 1)
act_recur_kernel(const float* __restrict__ W_halt,
                 const float* __restrict__ b_halt,
                 float* __restrict__ p_out,
                 float* __restrict__ n_out)
{
    extern __shared__ float sh[];
    float*  Wsh    = sh;                              // [KSP][HDIM] float2 pairs
    float4* sbuf0  = (float4*)(sh + WSH_FLOATS);      // [HDIM] s for 4 rows
    float4* sbuf1  = sbuf0 + HDIM;
    float* flag_sh  = sh + WSH_FLOATS + 2048;
    float* whalt_sh = flag_sh + HDIM;
    float* red      = whalt_sh + HDIM;    // [8 warps][4 rows]
    float* p_sh     = red + 32;
    float* hsum_s   = p_sh + 4;
    float* psum_s   = hsum_s + 4;
    float* nst_s    = psum_s + 4;
    float* rem_s    = nst_s + 4;
    int*   run_s    = (int*)(rem_s + 4);

    const int tid = threadIdx.x;
    const int rb  = blockIdx.x * 4;

    // stage smem weights in paired layout: Wsh[kp*512 + h*2 + b] = WhhT[2kp+b][h]
    for (int i = tid; i < WSH_FLOATS; i += 256) {
        int kp = i >> 9;
        int r  = i & 511;
        int h  = r >> 1;
        int b  = r & 1;
        Wsh[i] = g_WhhT[(2*kp + b)*HDIM + h];
    }
    float wreg[KR];
#pragma unroll
    for (int j = 0; j < KR; j++) wreg[j] = g_WhhT[(KS + j)*HDIM + tid];
    flag_sh[tid]  = g_flagv[tid];
    whalt_sh[tid] = W_halt[tid];
    const float bh = b_halt[0];
    sbuf0[tid] = make_float4(0.f, 0.f, 0.f, 0.f);     // s0 = 0
    __syncthreads();

    const float fl = flag_sh[tid];
    const float wh = whalt_sh[tid];
    const float2* Wp = (const float2*)Wsh;            // Wp[kp*HDIM + h]

    for (int t = 0; t < S_LEN; t++) {
        const float* prow = g_pre + ((size_t)(t*BATCH + rb))*HDIM + tid;
        const float pre0 = prow[0];
        const float pre1 = prow[HDIM];
        const float pre2 = prow[2*HDIM];
        const float pre3 = prow[3*HDIM];
        float sa0 = 0.f, sa1 = 0.f, sa2 = 0.f, sa3 = 0.f;

        if (tid < 4) {
            hsum_s[tid] = 0.f; psum_s[tid] = 0.f; nst_s[tid] = 0.f;
            rem_s[tid] = 0.f;  run_s[tid] = 1;
        }

        float4* sread  = sbuf0;
        float4* swrite = sbuf1;

        for (int n = 0; n < 10; n++) {
            const float flc = (n == 0) ? fl : 0.f;
            // split accumulators to break the FMA dependency chain
            float a0A = pre0 + flc, a1A = pre1 + flc, a2A = pre2 + flc, a3A = pre3 + flc;
            float a0B = 0.f, a1B = 0.f, a2B = 0.f, a3B = 0.f;

#pragma unroll 8
            for (int kp = 0; kp < KSP; kp++) {
                float2 w2 = Wp[kp*HDIM + tid];     // LDS.64, conflict-free
                float4 sA = sread[2*kp];           // LDS.128 broadcast
                float4 sB = sread[2*kp + 1];
                a0A = fmaf(sA.x, w2.x, a0A);
                a1A = fmaf(sA.y, w2.x, a1A);
                a2A = fmaf(sA.z, w2.x, a2A);
                a3A = fmaf(sA.w, w2.x, a3A);
                a0B = fmaf(sB.x, w2.y, a0B);
                a1B = fmaf(sB.y, w2.y, a1B);
                a2B = fmaf(sB.z, w2.y, a2B);
                a3B = fmaf(sB.w, w2.y, a3B);
            }
#pragma unroll
            for (int j = 0; j < KR; j++) {
                float4 s4 = sread[KS + j];
                float  w  = wreg[j];
                if (j & 1) {
                    a0B = fmaf(s4.x, w, a0B);
                    a1B = fmaf(s4.y, w, a1B);
                    a2B = fmaf(s4.z, w, a2B);
                    a3B = fmaf(s4.w, w, a3B);
                } else {
                    a0A = fmaf(s4.x, w, a0A);
                    a1A = fmaf(s4.y, w, a1A);
                    a2A = fmaf(s4.z, w, a2A);
                    a3A = fmaf(s4.w, w, a3A);
                }
            }

            const float sv0 = fast_tanh(a0A + a0B);
            const float sv1 = fast_tanh(a1A + a1B);
            const float sv2 = fast_tanh(a2A + a2B);
            const float sv3 = fast_tanh(a3A + a3B);
            swrite[tid] = make_float4(sv0, sv1, sv2, sv3);   // next step's s

            // halting dot: block reduction of wh*sv over h
            float q0 = wh*sv0, q1 = wh*sv1, q2 = wh*sv2, q3 = wh*sv3;
#pragma unroll
            for (int o = 16; o > 0; o >>= 1) {
                q0 += __shfl_xor_sync(0xffffffffu, q0, o);
                q1 += __shfl_xor_sync(0xffffffffu, q1, o);
                q2 += __shfl_xor_sync(0xffffffffu, q2, o);
                q3 += __shfl_xor_sync(0xffffffffu, q3, o);
            }
            if ((tid & 31) == 0) {
                int w8 = tid >> 5;
                red[w8*4+0] = q0; red[w8*4+1] = q1;
                red[w8*4+2] = q2; red[w8*4+3] = q3;
            }
            __syncthreads();                      // A: red + new s visible

            if (tid < 4) {
                float d = 0.f;
#pragma unroll
                for (int w8 = 0; w8 < 8; w8++) d += red[w8*4 + tid];
                float p = 0.f;
                if (run_s[tid]) {
                    float hh = __fdividef(1.f, 1.f + __expf(-(d + bh)));
                    float ns = hsum_s[tid] + hh;
                    bool halted = (ns >= 0.99f);          // 1.0 - EPS
                    p = halted ? (1.f - hsum_s[tid]) : hh;
                    psum_s[tid] += p;
                    nst_s[tid]  += 1.f;
                    if (halted) { rem_s[tid] = 1.f - hsum_s[tid]; run_s[tid] = 0; }
                    hsum_s[tid] = ns;
                }
                p_sh[tid] = p;
            }
            __syncthreads();                      // B: p + run visible

            sa0 = fmaf(p_sh[0], sv0, sa0);
            sa1 = fmaf(p_sh[1], sv1, sa1);
            sa2 = fmaf(p_sh[2], sv2, sa2);
            sa3 = fmaf(p_sh[3], sv3, sa3);

            float4* tmp = sread; sread = swrite; swrite = tmp;
            if (!(run_s[0] | run_s[1] | run_s[2] | run_s[3])) break;
        }

        // per-timestep epilogue
        float* so = g_sacc + ((size_t)(t*BATCH + rb))*HDIM + tid;
        so[0]       = sa0;
        so[HDIM]    = sa1;
        so[2*HDIM]  = sa2;
        so[3*HDIM]  = sa3;
        sbuf0[tid] = make_float4(sa0, sa1, sa2, sa3);  // carry = s_acc, into buf0
        if (tid < 4) {
            int row = t*BATCH + rb + tid;
            g_psum[row] = psum_s[tid];
            p_out[row]  = nst_s[tid] + rem_s[tid];
            n_out[row]  = nst_s[tid];
        }
        __syncthreads();
    }
}

// ---------------- launch ----------------
extern "C" void kernel_launch(void* const* d_in, const int* in_sizes, int n_in,
                              void* d_out, int out_size)
{
    const float* x      = (const float*)d_in[0];
    const float* W_ih   = (const float*)d_in[1];
    const float* b_ih   = (const float*)d_in[2];
    const float* W_hh   = (const float*)d_in[3];
    const float* b_hh   = (const float*)d_in[4];
    const float* W_halt = (const float*)d_in[5];
    const float* b_halt = (const float*)d_in[6];
    const float* W_out  = (const float*)d_in[7];
    const float* b_out  = (const float*)d_in[8];

    float* y     = (float*)d_out;                       // [S,B,O]
    float* p_out = y + (size_t)NROWS * ODIM;            // [S,B]
    float* n_out = p_out + NROWS;                       // [S,B]

    float *pre_ptr, *sacc_ptr, *wihT_ptr, *woutT_ptr, *bias1_ptr, *psum_ptr;
    cudaGetSymbolAddress((void**)&pre_ptr,   g_pre);
    cudaGetSymbolAddress((void**)&sacc_ptr,  g_sacc);
    cudaGetSymbolAddress((void**)&wihT_ptr,  g_WihT);
    cudaGetSymbolAddress((void**)&woutT_ptr, g_WoutT);
    cudaGetSymbolAddress((void**)&bias1_ptr, g_bias1);
    cudaGetSymbolAddress((void**)&psum_ptr,  g_psum);

    const int recur_smem = RECUR_SMEM_FLOATS * (int)sizeof(float);
    cudaFuncSetAttribute(act_recur_kernel,
                         cudaFuncAttributeMaxDynamicSharedMemorySize, recur_smem);

    // 1) transposes + bias fold
    prep_kernel<<<(IDIM*HDIM + 255)/256, 256>>>(W_ih, b_ih, b_hh, W_hh, W_out);

    // 2) PRE = X @ WihT + (b_ih+b_hh)   [65536,512]@[512,256]
    {
        dim3 grid(HDIM/BN, NROWS/BM);
        sgemm_bias_kernel<<<grid, 256>>>(x, wihT_ptr, pre_ptr,
                                         bias1_ptr, nullptr, nullptr,
                                         NROWS, HDIM, IDIM);
    }

    // 3) sequential ACT recurrence (persistent, early-exit)
    act_recur_kernel<<<128, 256, recur_smem>>>(W_halt, b_halt, p_out, n_out);

    // 4) Y = SACC @ WoutT + psum * b_out   [65536,256]@[256,256]
    {
        dim3 grid(ODIM/BN, NROWS/BM);
        sgemm_bias_kernel<<<grid, 256>>>(sacc_ptr, woutT_ptr, y,
                                         nullptr, psum_ptr, b_out,
                                         NROWS, ODIM, HDIM);
    }
}

// round 7
// speedup vs baseline: 1.1964x; 1.1697x over previous
#include <cuda_runtime.h>
#include <math.h>

// Problem dims (fixed by the dataset)
#define S_LEN 128
#define BATCH 512
#define IDIM  512
#define HDIM  256
#define ODIM  256
#define NROWS (S_LEN*BATCH)   // 65536

// ---------------- scratch (static device arrays; no allocation) ----------------
__device__ float g_WihT[IDIM*HDIM];              // [k][h] transposed W_ih (first 512 cols)
__device__ float g_WhhT[HDIM*HDIM];              // [k][h]
__device__ float g_WoutT[HDIM*ODIM];             // [k][o]
__device__ float g_flagv[HDIM];                  // W_ih[:,512]
__device__ float g_bias1[HDIM];                  // b_ih + b_hh
__device__ float g_pre [(size_t)NROWS*HDIM];     // X @ WihT + bias1
__device__ float g_sacc[(size_t)NROWS*HDIM];     // sum_n p_n * s_n
__device__ float g_psum[NROWS];                  // sum_n p_n

__device__ __forceinline__ float fast_tanh(float x) {
    float xc = fminf(fmaxf(x, -10.f), 10.f);
    float e  = __expf(2.f * xc);
    return __fdividef(e - 1.f, e + 1.f);
}
__device__ __forceinline__ float fast_sigmoid(float x) {
    return __fdividef(1.f, 1.f + __expf(-x));
}

// ---------------- dummy (launch-index padding so ncu -s5 -c1 lands on recurrence) ----
__global__ void dummy_kernel() {}

// ---------------- prep: transposes + bias fold ----------------
__global__ void prep_kernel(const float* __restrict__ W_ih,
                            const float* __restrict__ b_ih,
                            const float* __restrict__ b_hh,
                            const float* __restrict__ W_hh,
                            const float* __restrict__ W_out)
{
    int idx = blockIdx.x * blockDim.x + threadIdx.x;
    if (idx < IDIM*HDIM) {
        int k = idx / HDIM, h = idx % HDIM;
        g_WihT[idx] = W_ih[h*(IDIM+1) + k];
    }
    if (idx < HDIM*HDIM) {
        int k = idx / HDIM, h = idx % HDIM;
        g_WhhT[idx]  = W_hh [h*HDIM + k];
        g_WoutT[idx] = W_out[h*HDIM + k];
    }
    if (idx < HDIM) {
        g_flagv[idx] = W_ih[idx*(IDIM+1) + IDIM];
        g_bias1[idx] = b_ih[idx] + b_hh[idx];
    }
}

// ---------------- fp32 SGEMM 128x128x16, TM=TN=8 (at fp32 FFMA roofline) ----------------
// C = A@B (+ biasN) (+ rowscale*bias2).  A:[M,K] B:[K,N] row-major.
#define BM 128
#define BN 128
#define BK 16

__global__ void __launch_bounds__(256)
sgemm_bias_kernel(const float* __restrict__ A, const float* __restrict__ B,
                  float* __restrict__ C,
                  const float* __restrict__ biasN,
                  const float* __restrict__ rowscale,
                  const float* __restrict__ bias2,
                  int M, int N, int K)
{
    __shared__ float As[BK][BM+4];
    __shared__ float Bs[BK][BN];

    const int tid = threadIdx.x;
    const int m0 = blockIdx.y * BM;
    const int n0 = blockIdx.x * BN;
    const int tx = tid & 15;           // n sub-tile 0..15
    const int ty = tid >> 4;           // m sub-tile 0..15

    const int aRow = tid >> 2;         // 0..63 (+64 second group)
    const int aCol = (tid & 3) * 4;    // 0,4,8,12
    const int bRow = tid >> 5;         // 0..7 (+8 second group)
    const int bCol = (tid & 31) * 4;

    float acc[8][8];
#pragma unroll
    for (int i = 0; i < 8; i++)
#pragma unroll
        for (int j = 0; j < 8; j++) acc[i][j] = 0.f;

    for (int k0 = 0; k0 < K; k0 += BK) {
        float4 a0 = *(const float4*)(A + (size_t)(m0 + aRow)      * K + k0 + aCol);
        float4 a1 = *(const float4*)(A + (size_t)(m0 + aRow + 64) * K + k0 + aCol);
        float4 b0 = *(const float4*)(B + (size_t)(k0 + bRow)     * N + n0 + bCol);
        float4 b1 = *(const float4*)(B + (size_t)(k0 + bRow + 8) * N + n0 + bCol);

        As[aCol+0][aRow] = a0.x; As[aCol+1][aRow] = a0.y;
        As[aCol+2][aRow] = a0.z; As[aCol+3][aRow] = a0.w;
        As[aCol+0][aRow+64] = a1.x; As[aCol+1][aRow+64] = a1.y;
        As[aCol+2][aRow+64] = a1.z; As[aCol+3][aRow+64] = a1.w;
        *(float4*)&Bs[bRow][bCol]     = b0;
        *(float4*)&Bs[bRow+8][bCol]   = b1;
        __syncthreads();

#pragma unroll
        for (int k = 0; k < BK; k++) {
            float4 av0 = *(const float4*)&As[k][ty*8];
            float4 av1 = *(const float4*)&As[k][ty*8 + 4];
            float4 bv0 = *(const float4*)&Bs[k][tx*8];
            float4 bv1 = *(const float4*)&Bs[k][tx*8 + 4];
            float av[8] = {av0.x, av0.y, av0.z, av0.w, av1.x, av1.y, av1.z, av1.w};
            float bv[8] = {bv0.x, bv0.y, bv0.z, bv0.w, bv1.x, bv1.y, bv1.z, bv1.w};
#pragma unroll
            for (int i = 0; i < 8; i++)
#pragma unroll
                for (int j = 0; j < 8; j++)
                    acc[i][j] = fmaf(av[i], bv[j], acc[i][j]);
        }
        __syncthreads();
    }

    const int nbase = n0 + tx*8;
    float bn[8] = {0,0,0,0,0,0,0,0};
    float c2[8] = {0,0,0,0,0,0,0,0};
    if (biasN) {
#pragma unroll
        for (int j = 0; j < 8; j++) bn[j] = biasN[nbase + j];
    }
    if (bias2) {
#pragma unroll
        for (int j = 0; j < 8; j++) c2[j] = bias2[nbase + j];
    }
#pragma unroll
    for (int i = 0; i < 8; i++) {
        int row = m0 + ty*8 + i;
        float rs = rowscale ? rowscale[row] : 0.f;
        float4 o0, o1;
        o0.x = acc[i][0] + bn[0] + rs*c2[0];  o0.y = acc[i][1] + bn[1] + rs*c2[1];
        o0.z = acc[i][2] + bn[2] + rs*c2[2];  o0.w = acc[i][3] + bn[3] + rs*c2[3];
        o1.x = acc[i][4] + bn[4] + rs*c2[4];  o1.y = acc[i][5] + bn[5] + rs*c2[5];
        o1.z = acc[i][6] + bn[6] + rs*c2[6];  o1.w = acc[i][7] + bn[7] + rs*c2[7];
        *(float4*)(C + (size_t)row*N + nbase)     = o0;
        *(float4*)(C + (size_t)row*N + nbase + 4) = o1;
    }
}

// ---------------- persistent ACT recurrence: k-split MAC, s in registers ----------------
// 128 blocks x 256 threads; block owns 4 batch rows for all 128 timesteps.
// Thread tid keeps s[h=tid] for its 4 rows in a register float4; since h and k
// index the same hidden space, warp w owns k-chunk [32w,32w+32) and broadcasts
// s[k] via __shfl_sync (NO smem s traffic). Lane l accumulates partials for the
// 8 h-columns {l+32j}; partials are reduced across the 8 warps through smem.
// Weight columns j=0,1 are register-cached (wreg[64]); j=2..7 live in smem.
#define WSH_ELEMS (HDIM*192)          // W_hh^T columns 64..255: 196608 B
#define PART_ELEMS (8*HDIM)           // float4 partials: [warp][h]: 32768 B
#define RECUR_SMEM_BYTES (WSH_ELEMS*4 + PART_ELEMS*16 + 8*16)

__global__ void __launch_bounds__(256, 1)
act_recur_kernel(const float* __restrict__ W_halt,
                 const float* __restrict__ b_halt,
                 float* __restrict__ p_out,
                 float* __restrict__ n_out)
{
    extern __shared__ float sh[];
    float*  Wsh  = sh;                               // [k][h-64] for h in [64,256)
    float4* part = (float4*)(sh + WSH_ELEMS);        // [8][HDIM]
    float4* red4 = part + PART_ELEMS;                // [8]

    const int tid = threadIdx.x;
    const int w   = tid >> 5;          // warp id = k-chunk owner
    const int l   = tid & 31;          // lane
    const int rb  = blockIdx.x * 4;    // first batch row of this block

    // stage smem weight columns 64..255: Wsh[k*192 + c] = WhhT[k*256 + 64 + c]
    for (int i = tid; i < WSH_ELEMS; i += 256) {
        int k = i / 192, c = i - k*192;
        Wsh[i] = g_WhhT[k*HDIM + 64 + c];
    }
    // register-cache weight columns h = l and h = l+32 for this warp's k-chunk
    float wreg[64];
#pragma unroll
    for (int m = 0; m < 32; m++) {
        wreg[2*m+0] = g_WhhT[(32*w + m)*HDIM + l];
        wreg[2*m+1] = g_WhhT[(32*w + m)*HDIM + l + 32];
    }
    const float fl = g_flagv[tid];
    const float wh = W_halt[tid];
    const float bh = b_halt[0];

    float4 s4 = make_float4(0.f, 0.f, 0.f, 0.f);   // s[h=tid], 4 rows (s0 = 0)
    __syncthreads();

    for (int t = 0; t < S_LEN; t++) {
        const float* prow = g_pre + ((size_t)(t*BATCH + rb))*HDIM + tid;
        const float4 pre4 = make_float4(prow[0], prow[HDIM], prow[2*HDIM], prow[3*HDIM]);

        float4 sa = make_float4(0.f, 0.f, 0.f, 0.f);
        float hsum0=0.f, hsum1=0.f, hsum2=0.f, hsum3=0.f;
        float psum0=0.f, psum1=0.f, psum2=0.f, psum3=0.f;
        float nst=0.f;                      // same for all rows until one halts
        float nst0=0.f, nst1=0.f, nst2=0.f, nst3=0.f;
        float rem0=0.f, rem1=0.f, rem2=0.f, rem3=0.f;
        int run = 0xF;
        (void)nst;

        for (int n = 0; n < 10; n++) {
            // ---- k-split MAC: partials for h = l + 32j over k in [32w, 32w+32) ----
            float4 acc[8];
#pragma unroll
            for (int j = 0; j < 8; j++) acc[j] = make_float4(0.f, 0.f, 0.f, 0.f);

            int base = (32*w)*192 + l;
#pragma unroll
            for (int m = 0; m < 32; m++) {
                float4 sk;
                sk.x = __shfl_sync(0xffffffffu, s4.x, m);
                sk.y = __shfl_sync(0xffffffffu, s4.y, m);
                sk.z = __shfl_sync(0xffffffffu, s4.z, m);
                sk.w = __shfl_sync(0xffffffffu, s4.w, m);
                const float w0 = wreg[2*m+0];
                const float w1 = wreg[2*m+1];
                acc[0].x = fmaf(sk.x, w0, acc[0].x);
                acc[0].y = fmaf(sk.y, w0, acc[0].y);
                acc[0].z = fmaf(sk.z, w0, acc[0].z);
                acc[0].w = fmaf(sk.w, w0, acc[0].w);
                acc[1].x = fmaf(sk.x, w1, acc[1].x);
                acc[1].y = fmaf(sk.y, w1, acc[1].y);
                acc[1].z = fmaf(sk.z, w1, acc[1].z);
                acc[1].w = fmaf(sk.w, w1, acc[1].w);
#pragma unroll
                for (int j = 2; j < 8; j++) {
                    const float wv = Wsh[base + 32*(j-2)];   // bank = l, conflict-free
                    acc[j].x = fmaf(sk.x, wv, acc[j].x);
                    acc[j].y = fmaf(sk.y, wv, acc[j].y);
                    acc[j].z = fmaf(sk.z, wv, acc[j].z);
                    acc[j].w = fmaf(sk.w, wv, acc[j].w);
                }
                base += 192;
            }
            // store partials: part[w][l+32j]
#pragma unroll
            for (int j = 0; j < 8; j++)
                part[w*HDIM + l + 32*j] = acc[j];
            __syncthreads();                       // sync 1: partials visible

            // ---- h-owner: sum partials, add pre(+flag), tanh ----
            float4 d = pre4;
            if (n == 0) { d.x += fl; d.y += fl; d.z += fl; d.w += fl; }
#pragma unroll
            for (int ww = 0; ww < 8; ww++) {
                float4 pv = part[ww*HDIM + tid];
                d.x += pv.x; d.y += pv.y; d.z += pv.z; d.w += pv.w;
            }
            float4 sv;
            sv.x = fast_tanh(d.x);
            sv.y = fast_tanh(d.y);
            sv.z = fast_tanh(d.z);
            sv.w = fast_tanh(d.w);

            // ---- halting dot: warp reduce wh*sv, lane0 -> red4[w] ----
            float q0 = wh*sv.x, q1 = wh*sv.y, q2 = wh*sv.z, q3 = wh*sv.w;
#pragma unroll
            for (int o = 16; o > 0; o >>= 1) {
                q0 += __shfl_xor_sync(0xffffffffu, q0, o);
                q1 += __shfl_xor_sync(0xffffffffu, q1, o);
                q2 += __shfl_xor_sync(0xffffffffu, q2, o);
                q3 += __shfl_xor_sync(0xffffffffu, q3, o);
            }
            if (l == 0) red4[w] = make_float4(q0, q1, q2, q3);
            __syncthreads();                       // sync 2: red visible

            // ---- redundant halting update (all threads, deterministic) ----
            float d0=0.f, d1=0.f, d2=0.f, d3=0.f;
#pragma unroll
            for (int ww = 0; ww < 8; ww++) {
                float4 rv = red4[ww];
                d0 += rv.x; d1 += rv.y; d2 += rv.z; d3 += rv.w;
            }
            float p0=0.f, p1=0.f, p2=0.f, p3=0.f;
            if (run & 1) {
                float hh = fast_sigmoid(d0 + bh);
                float ns = hsum0 + hh;
                bool halted = (ns >= 0.99f);
                p0 = halted ? (1.f - hsum0) : hh;
                psum0 += p0; nst0 += 1.f;
                if (halted) { rem0 = 1.f - hsum0; run &= ~1; }
                hsum0 = ns;
            }
            if (run & 2) {
                float hh = fast_sigmoid(d1 + bh);
                float ns = hsum1 + hh;
                bool halted = (ns >= 0.99f);
                p1 = halted ? (1.f - hsum1) : hh;
                psum1 += p1; nst1 += 1.f;
                if (halted) { rem1 = 1.f - hsum1; run &= ~2; }
                hsum1 = ns;
            }
            if (run & 4) {
                float hh = fast_sigmoid(d2 + bh);
                float ns = hsum2 + hh;
                bool halted = (ns >= 0.99f);
                p2 = halted ? (1.f - hsum2) : hh;
                psum2 += p2; nst2 += 1.f;
                if (halted) { rem2 = 1.f - hsum2; run &= ~4; }
                hsum2 = ns;
            }
            if (run & 8) {
                float hh = fast_sigmoid(d3 + bh);
                float ns = hsum3 + hh;
                bool halted = (ns >= 0.99f);
                p3 = halted ? (1.f - hsum3) : hh;
                psum3 += p3; nst3 += 1.f;
                if (halted) { rem3 = 1.f - hsum3; run &= ~8; }
                hsum3 = ns;
            }

            sa.x = fmaf(p0, sv.x, sa.x);
            sa.y = fmaf(p1, sv.y, sa.y);
            sa.z = fmaf(p2, sv.z, sa.z);
            sa.w = fmaf(p3, sv.w, sa.w);
            s4 = sv;                                // next ponder step's s (registers!)

            if (run == 0) break;                    // uniform across block
        }

        // per-timestep epilogue (no extra sync needed: s carry is in registers,
        // part/red reuse is protected by the in-step sync pair)
        float* so = g_sacc + ((size_t)(t*BATCH + rb))*HDIM + tid;
        so[0]       = sa.x;
        so[HDIM]    = sa.y;
        so[2*HDIM]  = sa.z;
        so[3*HDIM]  = sa.w;
        s4 = sa;                                    // carry = s_acc
        if (tid < 4) {
            int row = t*BATCH + rb + tid;
            float ps  = (tid==0) ? psum0 : (tid==1) ? psum1 : (tid==2) ? psum2 : psum3;
            float nsv = (tid==0) ? nst0  : (tid==1) ? nst1  : (tid==2) ? nst2  : nst3;
            float rmv = (tid==0) ? rem0  : (tid==1) ? rem1  : (tid==2) ? rem2  : rem3;
            g_psum[row] = ps;
            p_out[row]  = nsv + rmv;
            n_out[row]  = nsv;
        }
    }
}

// ---------------- launch ----------------
extern "C" void kernel_launch(void* const* d_in, const int* in_sizes, int n_in,
                              void* d_out, int out_size)
{
    const float* x      = (const float*)d_in[0];
    const float* W_ih   = (const float*)d_in[1];
    const float* b_ih   = (const float*)d_in[2];
    const float* W_hh   = (const float*)d_in[3];
    const float* b_hh   = (const float*)d_in[4];
    const float* W_halt = (const float*)d_in[5];
    const float* b_halt = (const float*)d_in[6];
    const float* W_out  = (const float*)d_in[7];
    const float* b_out  = (const float*)d_in[8];

    float* y     = (float*)d_out;                       // [S,B,O]
    float* p_out = y + (size_t)NROWS * ODIM;            // [S,B]
    float* n_out = p_out + NROWS;                       // [S,B]

    float *pre_ptr, *sacc_ptr, *wihT_ptr, *woutT_ptr, *bias1_ptr, *psum_ptr;
    cudaGetSymbolAddress((void**)&pre_ptr,   g_pre);
    cudaGetSymbolAddress((void**)&sacc_ptr,  g_sacc);
    cudaGetSymbolAddress((void**)&wihT_ptr,  g_WihT);
    cudaGetSymbolAddress((void**)&woutT_ptr, g_WoutT);
    cudaGetSymbolAddress((void**)&bias1_ptr, g_bias1);
    cudaGetSymbolAddress((void**)&psum_ptr,  g_psum);

    cudaFuncSetAttribute(act_recur_kernel,
                         cudaFuncAttributeMaxDynamicSharedMemorySize, RECUR_SMEM_BYTES);

    // 1) transposes + bias fold                               (launch idx 0)
    prep_kernel<<<(IDIM*HDIM + 255)/256, 256>>>(W_ih, b_ih, b_hh, W_hh, W_out);

    // 2) PRE = X @ WihT + (b_ih+b_hh)   [65536,512]@[512,256] (launch idx 1)
    {
        dim3 grid(HDIM/BN, NROWS/BM);
        sgemm_bias_kernel<<<grid, 256>>>(x, wihT_ptr, pre_ptr,
                                         bias1_ptr, nullptr, nullptr,
                                         NROWS, HDIM, IDIM);
    }

    // padding launches so ncu (-s 5 -c 1) profiles the recurrence (idx 2,3,4)
    dummy_kernel<<<1, 32>>>();
    dummy_kernel<<<1, 32>>>();
    dummy_kernel<<<1, 32>>>();

    // 3) sequential ACT recurrence (persistent, early-exit)   (launch idx 5)
    act_recur_kernel<<<128, 256, RECUR_SMEM_BYTES>>>(W_halt, b_halt, p_out, n_out);

    // 4) Y = SACC @ WoutT + psum * b_out   [65536,256]@[256,256] (launch idx 6)
    {
        dim3 grid(ODIM/BN, NROWS/BM);
        sgemm_bias_kernel<<<grid, 256>>>(sacc_ptr, woutT_ptr, y,
                                         nullptr, psum_ptr, b_out,
                                         NROWS, ODIM, HDIM);
    }
}

// round 8
// speedup vs baseline: 1.2130x; 1.0139x over previous
#include <cuda_runtime.h>
#include <math.h>

// Problem dims (fixed by the dataset)
#define S_LEN 128
#define BATCH 512
#define IDIM  512
#define HDIM  256
#define ODIM  256
#define NROWS (S_LEN*BATCH)   // 65536

// ---------------- scratch (static device arrays; no allocation) ----------------
__device__ float g_WihT[IDIM*HDIM];              // [k][h] transposed W_ih (first 512 cols)
__device__ float g_WhhT[HDIM*HDIM];              // [k][h]
__device__ float g_WoutT[HDIM*ODIM];             // [k][o]
__device__ float g_flagv[HDIM];                  // W_ih[:,512]
__device__ float g_bias1[HDIM];                  // b_ih + b_hh
__device__ float g_pre [(size_t)NROWS*HDIM];     // X @ WihT + bias1
__device__ float g_sacc[(size_t)NROWS*HDIM];     // sum_n p_n * s_n
__device__ float g_psum[NROWS];                  // sum_n p_n

__device__ __forceinline__ float fast_tanh(float x) {
    float xc = fminf(fmaxf(x, -10.f), 10.f);
    float e  = __expf(2.f * xc);
    return __fdividef(e - 1.f, e + 1.f);
}
__device__ __forceinline__ float fast_sigmoid(float x) {
    return __fdividef(1.f, 1.f + __expf(-x));
}

// ---------------- dummy (launch-index padding; harness poison-fill is idx 0) ----
__global__ void dummy_kernel() {}

// ---------------- prep: transposes + bias fold ----------------
__global__ void prep_kernel(const float* __restrict__ W_ih,
                            const float* __restrict__ b_ih,
                            const float* __restrict__ b_hh,
                            const float* __restrict__ W_hh,
                            const float* __restrict__ W_out)
{
    int idx = blockIdx.x * blockDim.x + threadIdx.x;
    if (idx < IDIM*HDIM) {
        int k = idx / HDIM, h = idx % HDIM;
        g_WihT[idx] = W_ih[h*(IDIM+1) + k];
    }
    if (idx < HDIM*HDIM) {
        int k = idx / HDIM, h = idx % HDIM;
        g_WhhT[idx]  = W_hh [h*HDIM + k];
        g_WoutT[idx] = W_out[h*HDIM + k];
    }
    if (idx < HDIM) {
        g_flagv[idx] = W_ih[idx*(IDIM+1) + IDIM];
        g_bias1[idx] = b_ih[idx] + b_hh[idx];
    }
}

// ---------------- fp32 SGEMM 128x128x16, TM=TN=8 (at fp32 FFMA roofline) ----------------
#define BM 128
#define BN 128
#define BK 16

__global__ void __launch_bounds__(256)
sgemm_bias_kernel(const float* __restrict__ A, const float* __restrict__ B,
                  float* __restrict__ C,
                  const float* __restrict__ biasN,
                  const float* __restrict__ rowscale,
                  const float* __restrict__ bias2,
                  int M, int N, int K)
{
    __shared__ float As[BK][BM+4];
    __shared__ float Bs[BK][BN];

    const int tid = threadIdx.x;
    const int m0 = blockIdx.y * BM;
    const int n0 = blockIdx.x * BN;
    const int tx = tid & 15;
    const int ty = tid >> 4;

    const int aRow = tid >> 2;
    const int aCol = (tid & 3) * 4;
    const int bRow = tid >> 5;
    const int bCol = (tid & 31) * 4;

    float acc[8][8];
#pragma unroll
    for (int i = 0; i < 8; i++)
#pragma unroll
        for (int j = 0; j < 8; j++) acc[i][j] = 0.f;

    for (int k0 = 0; k0 < K; k0 += BK) {
        float4 a0 = *(const float4*)(A + (size_t)(m0 + aRow)      * K + k0 + aCol);
        float4 a1 = *(const float4*)(A + (size_t)(m0 + aRow + 64) * K + k0 + aCol);
        float4 b0 = *(const float4*)(B + (size_t)(k0 + bRow)     * N + n0 + bCol);
        float4 b1 = *(const float4*)(B + (size_t)(k0 + bRow + 8) * N + n0 + bCol);

        As[aCol+0][aRow] = a0.x; As[aCol+1][aRow] = a0.y;
        As[aCol+2][aRow] = a0.z; As[aCol+3][aRow] = a0.w;
        As[aCol+0][aRow+64] = a1.x; As[aCol+1][aRow+64] = a1.y;
        As[aCol+2][aRow+64] = a1.z; As[aCol+3][aRow+64] = a1.w;
        *(float4*)&Bs[bRow][bCol]     = b0;
        *(float4*)&Bs[bRow+8][bCol]   = b1;
        __syncthreads();

#pragma unroll
        for (int k = 0; k < BK; k++) {
            float4 av0 = *(const float4*)&As[k][ty*8];
            float4 av1 = *(const float4*)&As[k][ty*8 + 4];
            float4 bv0 = *(const float4*)&Bs[k][tx*8];
            float4 bv1 = *(const float4*)&Bs[k][tx*8 + 4];
            float av[8] = {av0.x, av0.y, av0.z, av0.w, av1.x, av1.y, av1.z, av1.w};
            float bv[8] = {bv0.x, bv0.y, bv0.z, bv0.w, bv1.x, bv1.y, bv1.z, bv1.w};
#pragma unroll
            for (int i = 0; i < 8; i++)
#pragma unroll
                for (int j = 0; j < 8; j++)
                    acc[i][j] = fmaf(av[i], bv[j], acc[i][j]);
        }
        __syncthreads();
    }

    const int nbase = n0 + tx*8;
    float bn[8] = {0,0,0,0,0,0,0,0};
    float c2[8] = {0,0,0,0,0,0,0,0};
    if (biasN) {
#pragma unroll
        for (int j = 0; j < 8; j++) bn[j] = biasN[nbase + j];
    }
    if (bias2) {
#pragma unroll
        for (int j = 0; j < 8; j++) c2[j] = bias2[nbase + j];
    }
#pragma unroll
    for (int i = 0; i < 8; i++) {
        int row = m0 + ty*8 + i;
        float rs = rowscale ? rowscale[row] : 0.f;
        float4 o0, o1;
        o0.x = acc[i][0] + bn[0] + rs*c2[0];  o0.y = acc[i][1] + bn[1] + rs*c2[1];
        o0.z = acc[i][2] + bn[2] + rs*c2[2];  o0.w = acc[i][3] + bn[3] + rs*c2[3];
        o1.x = acc[i][4] + bn[4] + rs*c2[4];  o1.y = acc[i][5] + bn[5] + rs*c2[5];
        o1.z = acc[i][6] + bn[6] + rs*c2[6];  o1.w = acc[i][7] + bn[7] + rs*c2[7];
        *(float4*)(C + (size_t)row*N + nbase)     = o0;
        *(float4*)(C + (size_t)row*N + nbase + 4) = o1;
    }
}

// ---------------- persistent ACT recurrence v3: 512 threads, k-split x h-split ----------
// 128 blocks x 512 threads (16 warps); block owns 4 batch rows for all 128 timesteps.
// s[h] (4 rows, float4) lives in smem; warp w = (c = w&7, g = w>>3): k-chunk
// [32c,32c+32), h-columns h = l + 32*(4g+j), j=0..3. s[k] read via LDS.128
// broadcast (no shfl). Weights: j=0,1 register-cached (64 regs); j=2,3 from a
// 128-column smem image. Partials [8 chunks][256 h] reduced by h-owner threads.
#define WSH_ELEMS  (HDIM*128)              // 131072 B
#define PART_FL4   (8*HDIM)                // 32768 B
#define RECUR_SMEM_BYTES (WSH_ELEMS*4 + PART_FL4*16 + HDIM*16 + 8*16 + 64)

__global__ void __launch_bounds__(512, 1)
act_recur_kernel(const float* __restrict__ W_halt,
                 const float* __restrict__ b_halt,
                 float* __restrict__ p_out,
                 float* __restrict__ n_out)
{
    extern __shared__ float sh[];
    float*  Wsh  = sh;                                // [k][cc] cc<64: h=cc+64; else h=cc+128
    float4* part = (float4*)(sh + WSH_ELEMS);         // [8][HDIM]
    float4* s_sm = part + PART_FL4;                   // [HDIM]: s[h] for 4 rows
    float4* red4 = s_sm + HDIM;                       // [8]

    const int tid = threadIdx.x;
    const int w   = tid >> 5;
    const int l   = tid & 31;
    const int c   = w & 7;             // k-chunk
    const int g   = w >> 3;            // h-half
    const int rb  = blockIdx.x * 4;    // first batch row

    // stage smem weight image: columns h in [64,128) U [192,256)
    for (int i = tid; i < WSH_ELEMS; i += 512) {
        int k = i >> 7, cc = i & 127;
        int h = (cc < 64) ? (cc + 64) : (cc + 128);
        Wsh[i] = g_WhhT[k*HDIM + h];
    }
    // register-cache weight columns j=0,1: h = l+128g, l+32+128g
    float wreg[64];
    {
        const int kb = 32*c;
#pragma unroll
        for (int m = 0; m < 32; m++) {
            wreg[2*m+0] = g_WhhT[(kb+m)*HDIM + l + 128*g];
            wreg[2*m+1] = g_WhhT[(kb+m)*HDIM + l + 128*g + 32];
        }
    }
    const float fl = (tid < HDIM) ? g_flagv[tid] : 0.f;
    const float wh = (tid < HDIM) ? W_halt[tid] : 0.f;
    const float bh = b_halt[0];
    if (tid < HDIM) s_sm[tid] = make_float4(0.f, 0.f, 0.f, 0.f);   // s0 = 0
    __syncthreads();

    for (int t = 0; t < S_LEN; t++) {
        float4 pre4 = make_float4(0.f, 0.f, 0.f, 0.f);
        if (tid < HDIM) {
            const float* prow = g_pre + ((size_t)(t*BATCH + rb))*HDIM + tid;
            pre4 = make_float4(prow[0], prow[HDIM], prow[2*HDIM], prow[3*HDIM]);
        }

        float4 sa = make_float4(0.f, 0.f, 0.f, 0.f);
        float hsum0=0.f, hsum1=0.f, hsum2=0.f, hsum3=0.f;
        float psum0=0.f, psum1=0.f, psum2=0.f, psum3=0.f;
        float nst0=0.f, nst1=0.f, nst2=0.f, nst3=0.f;
        float rem0=0.f, rem1=0.f, rem2=0.f, rem3=0.f;
        int run = 0xF;

        for (int n = 0; n < 10; n++) {
            // ---- phase 1: k-split MAC. Partials for h = l+32(4g+j), k in [32c,+32) ----
            float4 a0 = make_float4(0.f,0.f,0.f,0.f);
            float4 a1 = make_float4(0.f,0.f,0.f,0.f);
            float4 a2 = make_float4(0.f,0.f,0.f,0.f);
            float4 a3 = make_float4(0.f,0.f,0.f,0.f);
            const int kb = 32*c;
            const int wbase = l + 64*g;
#pragma unroll
            for (int m = 0; m < 32; m++) {
                const float4 sk = s_sm[kb + m];           // LDS.128 broadcast
                const float w0 = wreg[2*m+0];
                const float w1 = wreg[2*m+1];
                const float w2 = Wsh[(kb+m)*128 + wbase];        // conflict-free
                const float w3 = Wsh[(kb+m)*128 + wbase + 32];
                a0.x = fmaf(sk.x, w0, a0.x); a0.y = fmaf(sk.y, w0, a0.y);
                a0.z = fmaf(sk.z, w0, a0.z); a0.w = fmaf(sk.w, w0, a0.w);
                a1.x = fmaf(sk.x, w1, a1.x); a1.y = fmaf(sk.y, w1, a1.y);
                a1.z = fmaf(sk.z, w1, a1.z); a1.w = fmaf(sk.w, w1, a1.w);
                a2.x = fmaf(sk.x, w2, a2.x); a2.y = fmaf(sk.y, w2, a2.y);
                a2.z = fmaf(sk.z, w2, a2.z); a2.w = fmaf(sk.w, w2, a2.w);
                a3.x = fmaf(sk.x, w3, a3.x); a3.y = fmaf(sk.y, w3, a3.y);
                a3.z = fmaf(sk.z, w3, a3.z); a3.w = fmaf(sk.w, w3, a3.w);
            }
            {
                const int hb = l + 128*g;
                part[c*HDIM + hb      ] = a0;
                part[c*HDIM + hb + 32 ] = a1;
                part[c*HDIM + hb + 64 ] = a2;
                part[c*HDIM + hb + 96 ] = a3;
            }
            __syncthreads();                       // partials visible

            // ---- phase 2 (h-owners tid<256): reduce, tanh, store s, halting dot ----
            if (tid < HDIM) {
                float4 d = pre4;
                if (n == 0) { d.x += fl; d.y += fl; d.z += fl; d.w += fl; }
#pragma unroll
                for (int cc = 0; cc < 8; cc++) {
                    float4 pv = part[cc*HDIM + tid];
                    d.x += pv.x; d.y += pv.y; d.z += pv.z; d.w += pv.w;
                }
                float4 sv;
                sv.x = fast_tanh(d.x);
                sv.y = fast_tanh(d.y);
                sv.z = fast_tanh(d.z);
                sv.w = fast_tanh(d.w);
                s_sm[tid] = sv;                    // next ponder step's s

                float q0 = wh*sv.x, q1 = wh*sv.y, q2 = wh*sv.z, q3 = wh*sv.w;
#pragma unroll
                for (int o = 16; o > 0; o >>= 1) {
                    q0 += __shfl_xor_sync(0xffffffffu, q0, o);
                    q1 += __shfl_xor_sync(0xffffffffu, q1, o);
                    q2 += __shfl_xor_sync(0xffffffffu, q2, o);
                    q3 += __shfl_xor_sync(0xffffffffu, q3, o);
                }
                if (l == 0) red4[w] = make_float4(q0, q1, q2, q3);
            }
            __syncthreads();                       // red + s visible

            // ---- all threads: redundant halting update (deterministic) ----
            float d0=0.f, d1=0.f, d2=0.f, d3=0.f;
#pragma unroll
            for (int ww = 0; ww < 8; ww++) {
                float4 rv = red4[ww];
                d0 += rv.x; d1 += rv.y; d2 += rv.z; d3 += rv.w;
            }
            float p0=0.f, p1=0.f, p2=0.f, p3=0.f;
            if (run & 1) {
                float hh = fast_sigmoid(d0 + bh);
                float ns = hsum0 + hh;
                bool halted = (ns >= 0.99f);
                p0 = halted ? (1.f - hsum0) : hh;
                psum0 += p0; nst0 += 1.f;
                if (halted) { rem0 = 1.f - hsum0; run &= ~1; }
                hsum0 = ns;
            }
            if (run & 2) {
                float hh = fast_sigmoid(d1 + bh);
                float ns = hsum1 + hh;
                bool halted = (ns >= 0.99f);
                p1 = halted ? (1.f - hsum1) : hh;
                psum1 += p1; nst1 += 1.f;
                if (halted) { rem1 = 1.f - hsum1; run &= ~2; }
                hsum1 = ns;
            }
            if (run & 4) {
                float hh = fast_sigmoid(d2 + bh);
                float ns = hsum2 + hh;
                bool halted = (ns >= 0.99f);
                p2 = halted ? (1.f - hsum2) : hh;
                psum2 += p2; nst2 += 1.f;
                if (halted) { rem2 = 1.f - hsum2; run &= ~4; }
                hsum2 = ns;
            }
            if (run & 8) {
                float hh = fast_sigmoid(d3 + bh);
                float ns = hsum3 + hh;
                bool halted = (ns >= 0.99f);
                p3 = halted ? (1.f - hsum3) : hh;
                psum3 += p3; nst3 += 1.f;
                if (halted) { rem3 = 1.f - hsum3; run &= ~8; }
                hsum3 = ns;
            }

            if (tid < HDIM) {
                float4 sv = s_sm[tid];
                sa.x = fmaf(p0, sv.x, sa.x);
                sa.y = fmaf(p1, sv.y, sa.y);
                sa.z = fmaf(p2, sv.z, sa.z);
                sa.w = fmaf(p3, sv.w, sa.w);
            }
            if (run == 0) break;                   // uniform across block
        }

        // per-timestep epilogue
        if (tid < HDIM) {
            float* so = g_sacc + ((size_t)(t*BATCH + rb))*HDIM + tid;
            so[0]       = sa.x;
            so[HDIM]    = sa.y;
            so[2*HDIM]  = sa.z;
            so[3*HDIM]  = sa.w;
            s_sm[tid] = sa;                        // carry = s_acc
        }
        if (tid < 4) {
            int row = t*BATCH + rb + tid;
            float ps  = (tid==0) ? psum0 : (tid==1) ? psum1 : (tid==2) ? psum2 : psum3;
            float nsv = (tid==0) ? nst0  : (tid==1) ? nst1  : (tid==2) ? nst2  : nst3;
            float rmv = (tid==0) ? rem0  : (tid==1) ? rem1  : (tid==2) ? rem2  : rem3;
            g_psum[row] = ps;
            p_out[row]  = nsv + rmv;
            n_out[row]  = nsv;
        }
        __syncthreads();                           // s carry visible before next t
    }
}

// ---------------- launch ----------------
extern "C" void kernel_launch(void* const* d_in, const int* in_sizes, int n_in,
                              void* d_out, int out_size)
{
    const float* x      = (const float*)d_in[0];
    const float* W_ih   = (const float*)d_in[1];
    const float* b_ih   = (const float*)d_in[2];
    const float* W_hh   = (const float*)d_in[3];
    const float* b_hh   = (const float*)d_in[4];
    const float* W_halt = (const float*)d_in[5];
    const float* b_halt = (const float*)d_in[6];
    const float* W_out  = (const float*)d_in[7];
    const float* b_out  = (const float*)d_in[8];

    float* y     = (float*)d_out;                       // [S,B,O]
    float* p_out = y + (size_t)NROWS * ODIM;            // [S,B]
    float* n_out = p_out + NROWS;                       // [S,B]

    float *pre_ptr, *sacc_ptr, *wihT_ptr, *woutT_ptr, *bias1_ptr, *psum_ptr;
    cudaGetSymbolAddress((void**)&pre_ptr,   g_pre);
    cudaGetSymbolAddress((void**)&sacc_ptr,  g_sacc);
    cudaGetSymbolAddress((void**)&wihT_ptr,  g_WihT);
    cudaGetSymbolAddress((void**)&woutT_ptr, g_WoutT);
    cudaGetSymbolAddress((void**)&bias1_ptr, g_bias1);
    cudaGetSymbolAddress((void**)&psum_ptr,  g_psum);

    cudaFuncSetAttribute(act_recur_kernel,
                         cudaFuncAttributeMaxDynamicSharedMemorySize, RECUR_SMEM_BYTES);

    // local idx 0 (global 1 after harness poison fill)
    prep_kernel<<<(IDIM*HDIM + 255)/256, 256>>>(W_ih, b_ih, b_hh, W_hh, W_out);

    // local idx 1: PRE = X @ WihT + (b_ih+b_hh)
    {
        dim3 grid(HDIM/BN, NROWS/BM);
        sgemm_bias_kernel<<<grid, 256>>>(x, wihT_ptr, pre_ptr,
                                         bias1_ptr, nullptr, nullptr,
                                         NROWS, HDIM, IDIM);
    }

    // local idx 2,3: padding so recurrence lands at global idx 5 for ncu -s5 -c1
    dummy_kernel<<<1, 32>>>();
    dummy_kernel<<<1, 32>>>();

    // local idx 4 (global 5): sequential ACT recurrence
    act_recur_kernel<<<128, 512, RECUR_SMEM_BYTES>>>(W_halt, b_halt, p_out, n_out);

    // local idx 5: Y = SACC @ WoutT + psum * b_out
    {
        dim3 grid(ODIM/BN, NROWS/BM);
        sgemm_bias_kernel<<<grid, 256>>>(sacc_ptr, woutT_ptr, y,
                                         nullptr, psum_ptr, b_out,
                                         NROWS, ODIM, HDIM);
    }
}

// round 10
// speedup vs baseline: 1.3353x; 1.1008x over previous
#include <cuda_runtime.h>
#include <math.h>

// Problem dims (fixed by the dataset)
#define S_LEN 128
#define BATCH 512
#define IDIM  512
#define HDIM  256
#define ODIM  256
#define NROWS (S_LEN*BATCH)   // 65536

// ---------------- scratch (static device arrays; no allocation) ----------------
__device__ float g_WihT[IDIM*HDIM];              // [k][h] transposed W_ih (first 512 cols)
__device__ float g_WhhT[HDIM*HDIM];              // [k][h]
__device__ float g_WoutT[HDIM*ODIM];             // [k][o]
__device__ float g_flagv[HDIM];                  // W_ih[:,512]
__device__ float g_bias1[HDIM];                  // b_ih + b_hh
__device__ float g_pre [(size_t)NROWS*HDIM];     // X @ WihT + bias1
__device__ float g_sacc[(size_t)NROWS*HDIM];     // sum_n p_n * s_n
__device__ float g_psum[NROWS];                  // sum_n p_n

__device__ __forceinline__ float fast_tanh(float x) {
    float xc = fminf(fmaxf(x, -10.f), 10.f);
    float e  = __expf(2.f * xc);
    return __fdividef(e - 1.f, e + 1.f);
}
__device__ __forceinline__ float fast_sigmoid(float x) {
    return __fdividef(1.f, 1.f + __expf(-x));
}

// ---------------- dummy (launch-index padding; ncu global idx5 = local idx3) ----
__global__ void dummy_kernel() {}

// ---------------- prep: transposes + bias fold ----------------
__global__ void prep_kernel(const float* __restrict__ W_ih,
                            const float* __restrict__ b_ih,
                            const float* __restrict__ b_hh,
                            const float* __restrict__ W_hh,
                            const float* __restrict__ W_out)
{
    int idx = blockIdx.x * blockDim.x + threadIdx.x;
    if (idx < IDIM*HDIM) {
        int k = idx / HDIM, h = idx % HDIM;
        g_WihT[idx] = W_ih[h*(IDIM+1) + k];
    }
    if (idx < HDIM*HDIM) {
        int k = idx / HDIM, h = idx % HDIM;
        g_WhhT[idx]  = W_hh [h*HDIM + k];
        g_WoutT[idx] = W_out[h*HDIM + k];
    }
    if (idx < HDIM) {
        g_flagv[idx] = W_ih[idx*(IDIM+1) + IDIM];
        g_bias1[idx] = b_ih[idx] + b_hh[idx];
    }
}

// ---------------- fp32 SGEMM 128x128x16, TM=TN=8 ----------------
#define BM 128
#define BN 128
#define BK 16

__global__ void __launch_bounds__(256)
sgemm_bias_kernel(const float* __restrict__ A, const float* __restrict__ B,
                  float* __restrict__ C,
                  const float* __restrict__ biasN,
                  const float* __restrict__ rowscale,
                  const float* __restrict__ bias2,
                  int M, int N, int K)
{
    __shared__ float As[BK][BM+4];
    __shared__ float Bs[BK][BN];

    const int tid = threadIdx.x;
    const int m0 = blockIdx.y * BM;
    const int n0 = blockIdx.x * BN;
    const int tx = tid & 15;
    const int ty = tid >> 4;

    const int aRow = tid >> 2;
    const int aCol = (tid & 3) * 4;
    const int bRow = tid >> 5;
    const int bCol = (tid & 31) * 4;

    float acc[8][8];
#pragma unroll
    for (int i = 0; i < 8; i++)
#pragma unroll
        for (int j = 0; j < 8; j++) acc[i][j] = 0.f;

    for (int k0 = 0; k0 < K; k0 += BK) {
        float4 a0 = *(const float4*)(A + (size_t)(m0 + aRow)      * K + k0 + aCol);
        float4 a1 = *(const float4*)(A + (size_t)(m0 + aRow + 64) * K + k0 + aCol);
        float4 b0 = *(const float4*)(B + (size_t)(k0 + bRow)     * N + n0 + bCol);
        float4 b1 = *(const float4*)(B + (size_t)(k0 + bRow + 8) * N + n0 + bCol);

        As[aCol+0][aRow] = a0.x; As[aCol+1][aRow] = a0.y;
        As[aCol+2][aRow] = a0.z; As[aCol+3][aRow] = a0.w;
        As[aCol+0][aRow+64] = a1.x; As[aCol+1][aRow+64] = a1.y;
        As[aCol+2][aRow+64] = a1.z; As[aCol+3][aRow+64] = a1.w;
        *(float4*)&Bs[bRow][bCol]     = b0;
        *(float4*)&Bs[bRow+8][bCol]   = b1;
        __syncthreads();

#pragma unroll
        for (int k = 0; k < BK; k++) {
            float4 av0 = *(const float4*)&As[k][ty*8];
            float4 av1 = *(const float4*)&As[k][ty*8 + 4];
            float4 bv0 = *(const float4*)&Bs[k][tx*8];
            float4 bv1 = *(const float4*)&Bs[k][tx*8 + 4];
            float av[8] = {av0.x, av0.y, av0.z, av0.w, av1.x, av1.y, av1.z, av1.w};
            float bv[8] = {bv0.x, bv0.y, bv0.z, bv0.w, bv1.x, bv1.y, bv1.z, bv1.w};
#pragma unroll
            for (int i = 0; i < 8; i++)
#pragma unroll
                for (int j = 0; j < 8; j++)
                    acc[i][j] = fmaf(av[i], bv[j], acc[i][j]);
        }
        __syncthreads();
    }

    const int nbase = n0 + tx*8;
    float bn[8] = {0,0,0,0,0,0,0,0};
    float c2[8] = {0,0,0,0,0,0,0,0};
    if (biasN) {
#pragma unroll
        for (int j = 0; j < 8; j++) bn[j] = biasN[nbase + j];
    }
    if (bias2) {
#pragma unroll
        for (int j = 0; j < 8; j++) c2[j] = bias2[nbase + j];
    }
#pragma unroll
    for (int i = 0; i < 8; i++) {
        int row = m0 + ty*8 + i;
        float rs = rowscale ? rowscale[row] : 0.f;
        float4 o0, o1;
        o0.x = acc[i][0] + bn[0] + rs*c2[0];  o0.y = acc[i][1] + bn[1] + rs*c2[1];
        o0.z = acc[i][2] + bn[2] + rs*c2[2];  o0.w = acc[i][3] + bn[3] + rs*c2[3];
        o1.x = acc[i][4] + bn[4] + rs*c2[4];  o1.y = acc[i][5] + bn[5] + rs*c2[5];
        o1.z = acc[i][6] + bn[6] + rs*c2[6];  o1.w = acc[i][7] + bn[7] + rs*c2[7];
        *(float4*)(C + (size_t)row*N + nbase)     = o0;
        *(float4*)(C + (size_t)row*N + nbase + 4) = o1;
    }
}

// ---------------- persistent ACT recurrence v4: 256 threads, 8 cols/thread ------------
// 128 blocks x 256 threads (8 warps); block owns 4 batch rows for all 128 timesteps.
// LDS-bandwidth-optimized: each 16B s-broadcast load feeds 32 FMAs.
// Warp w owns k-chunk [32w,32w+32); lane l computes h = l+32j, j=0..7.
// Weight cols j=0..3 register-cached (wreg[128]); j=4..7 from smem float2 pairs.
// Partials [8 chunks][256 h] reduced by h-owner thread tid (tid==h).
#define W45_FL2  (HDIM*32)                 // 65536 B (cols l+128,l+160)
#define W67_FL2  (HDIM*32)                 // 65536 B (cols l+192,l+224)
#define PART_FL4 (8*HDIM)                  // 32768 B
#define RECUR_SMEM_BYTES (W45_FL2*8 + W67_FL2*8 + PART_FL4*16 + HDIM*16 + 8*16 + 64)

__global__ void __launch_bounds__(256, 1)
act_recur_kernel(const float* __restrict__ W_halt,
                 const float* __restrict__ b_halt,
                 float* __restrict__ p_out,
                 float* __restrict__ n_out)
{
    extern __shared__ float sh[];
    float2* W45  = (float2*)sh;                    // [256 k][32 l]
    float2* W67  = W45 + W45_FL2;                  // [256 k][32 l]
    float4* part = (float4*)(W67 + W67_FL2);       // [8][HDIM]
    float4* s_sm = part + PART_FL4;                // [HDIM]
    float4* red4 = s_sm + HDIM;                    // [8]

    const int tid = threadIdx.x;
    const int w   = tid >> 5;          // warp id = k-chunk
    const int l   = tid & 31;
    const int rb  = blockIdx.x * 4;    // first batch row
    const int kb  = 32*w;

    // stage smem weight pairs
    for (int i = tid; i < W45_FL2; i += 256) {
        int k = i >> 5, ll = i & 31;
        W45[i] = make_float2(g_WhhT[k*HDIM + 128 + ll], g_WhhT[k*HDIM + 160 + ll]);
        W67[i] = make_float2(g_WhhT[k*HDIM + 192 + ll], g_WhhT[k*HDIM + 224 + ll]);
    }
    // register-cache weight cols j=0..3: h = l, l+32, l+64, l+96
    float wreg[128];
#pragma unroll
    for (int m = 0; m < 32; m++) {
        wreg[4*m+0] = g_WhhT[(kb+m)*HDIM + l];
        wreg[4*m+1] = g_WhhT[(kb+m)*HDIM + l + 32];
        wreg[4*m+2] = g_WhhT[(kb+m)*HDIM + l + 64];
        wreg[4*m+3] = g_WhhT[(kb+m)*HDIM + l + 96];
    }
    const float fl = g_flagv[tid];
    const float wh = W_halt[tid];
    const float bh = b_halt[0];
    s_sm[tid] = make_float4(0.f, 0.f, 0.f, 0.f);   // s0 = 0
    __syncthreads();

    // prefetch first timestep's pre row
    const float* prow0 = g_pre + ((size_t)rb)*HDIM + tid;
    float4 pre4 = make_float4(prow0[0], prow0[HDIM], prow0[2*HDIM], prow0[3*HDIM]);

    for (int t = 0; t < S_LEN; t++) {
        // issue next timestep's pre loads early (consumed at loop end)
        float4 pre_next = make_float4(0.f, 0.f, 0.f, 0.f);
        if (t + 1 < S_LEN) {
            const float* pn = g_pre + ((size_t)((t+1)*BATCH + rb))*HDIM + tid;
            pre_next = make_float4(pn[0], pn[HDIM], pn[2*HDIM], pn[3*HDIM]);
        }

        float4 sa = make_float4(0.f, 0.f, 0.f, 0.f);
        float hsum0=0.f, hsum1=0.f, hsum2=0.f, hsum3=0.f;
        float psum0=0.f, psum1=0.f, psum2=0.f, psum3=0.f;
        float nst0=0.f, nst1=0.f, nst2=0.f, nst3=0.f;
        float rem0=0.f, rem1=0.f, rem2=0.f, rem3=0.f;
        int run = 0xF;

        for (int n = 0; n < 10; n++) {
            // ---- phase 1: k-split MAC. h = l+32j (j=0..7), k in [32w,+32) ----
            float4 a[8];
#pragma unroll
            for (int j = 0; j < 8; j++) a[j] = make_float4(0.f,0.f,0.f,0.f);

#pragma unroll
            for (int m = 0; m < 32; m++) {
                const float4 sk = s_sm[kb + m];             // LDS.128 broadcast
                const float2 p45 = W45[(kb+m)*32 + l];      // LDS.64 conflict-free
                const float2 p67 = W67[(kb+m)*32 + l];
                const float w0 = wreg[4*m+0], w1 = wreg[4*m+1];
                const float w2 = wreg[4*m+2], w3 = wreg[4*m+3];
                a[0].x = fmaf(sk.x,w0,a[0].x); a[0].y = fmaf(sk.y,w0,a[0].y);
                a[0].z = fmaf(sk.z,w0,a[0].z); a[0].w = fmaf(sk.w,w0,a[0].w);
                a[1].x = fmaf(sk.x,w1,a[1].x); a[1].y = fmaf(sk.y,w1,a[1].y);
                a[1].z = fmaf(sk.z,w1,a[1].z); a[1].w = fmaf(sk.w,w1,a[1].w);
                a[2].x = fmaf(sk.x,w2,a[2].x); a[2].y = fmaf(sk.y,w2,a[2].y);
                a[2].z = fmaf(sk.z,w2,a[2].z); a[2].w = fmaf(sk.w,w2,a[2].w);
                a[3].x = fmaf(sk.x,w3,a[3].x); a[3].y = fmaf(sk.y,w3,a[3].y);
                a[3].z = fmaf(sk.z,w3,a[3].z); a[3].w = fmaf(sk.w,w3,a[3].w);
                a[4].x = fmaf(sk.x,p45.x,a[4].x); a[4].y = fmaf(sk.y,p45.x,a[4].y);
                a[4].z = fmaf(sk.z,p45.x,a[4].z); a[4].w = fmaf(sk.w,p45.x,a[4].w);
                a[5].x = fmaf(sk.x,p45.y,a[5].x); a[5].y = fmaf(sk.y,p45.y,a[5].y);
                a[5].z = fmaf(sk.z,p45.y,a[5].z); a[5].w = fmaf(sk.w,p45.y,a[5].w);
                a[6].x = fmaf(sk.x,p67.x,a[6].x); a[6].y = fmaf(sk.y,p67.x,a[6].y);
                a[6].z = fmaf(sk.z,p67.x,a[6].z); a[6].w = fmaf(sk.w,p67.x,a[6].w);
                a[7].x = fmaf(sk.x,p67.y,a[7].x); a[7].y = fmaf(sk.y,p67.y,a[7].y);
                a[7].z = fmaf(sk.z,p67.y,a[7].z); a[7].w = fmaf(sk.w,p67.y,a[7].w);
            }
#pragma unroll
            for (int j = 0; j < 8; j++)
                part[w*HDIM + l + 32*j] = a[j];
            __syncthreads();                       // partials visible

            // ---- phase 2 (tid == h): reduce, tanh, store s, halting dot ----
            float4 d = pre4;
            if (n == 0) { d.x += fl; d.y += fl; d.z += fl; d.w += fl; }
#pragma unroll
            for (int cc = 0; cc < 8; cc++) {
                float4 pv = part[cc*HDIM + tid];
                d.x += pv.x; d.y += pv.y; d.z += pv.z; d.w += pv.w;
            }
            float4 sv;
            sv.x = fast_tanh(d.x);
            sv.y = fast_tanh(d.y);
            sv.z = fast_tanh(d.z);
            sv.w = fast_tanh(d.w);
            s_sm[tid] = sv;                        // next ponder step's s

            float q0 = wh*sv.x, q1 = wh*sv.y, q2 = wh*sv.z, q3 = wh*sv.w;
#pragma unroll
            for (int o = 16; o > 0; o >>= 1) {
                q0 += __shfl_xor_sync(0xffffffffu, q0, o);
                q1 += __shfl_xor_sync(0xffffffffu, q1, o);
                q2 += __shfl_xor_sync(0xffffffffu, q2, o);
                q3 += __shfl_xor_sync(0xffffffffu, q3, o);
            }
            if (l == 0) red4[w] = make_float4(q0, q1, q2, q3);
            __syncthreads();                       // red + s visible

            // ---- redundant halting update (all threads, deterministic) ----
            float d0=0.f, d1=0.f, d2=0.f, d3=0.f;
#pragma unroll
            for (int ww = 0; ww < 8; ww++) {
                float4 rv = red4[ww];
                d0 += rv.x; d1 += rv.y; d2 += rv.z; d3 += rv.w;
            }
            float p0=0.f, p1=0.f, p2=0.f, p3=0.f;
            if (run & 1) {
                float hh = fast_sigmoid(d0 + bh);
                float ns = hsum0 + hh;
                bool halted = (ns >= 0.99f);
                p0 = halted ? (1.f - hsum0) : hh;
                psum0 += p0; nst0 += 1.f;
                if (halted) { rem0 = 1.f - hsum0; run &= ~1; }
                hsum0 = ns;
            }
            if (run & 2) {
                float hh = fast_sigmoid(d1 + bh);
                float ns = hsum1 + hh;
                bool halted = (ns >= 0.99f);
                p1 = halted ? (1.f - hsum1) : hh;
                psum1 += p1; nst1 += 1.f;
                if (halted) { rem1 = 1.f - hsum1; run &= ~2; }
                hsum1 = ns;
            }
            if (run & 4) {
                float hh = fast_sigmoid(d2 + bh);
                float ns = hsum2 + hh;
                bool halted = (ns >= 0.99f);
                p2 = halted ? (1.f - hsum2) : hh;
                psum2 += p2; nst2 += 1.f;
                if (halted) { rem2 = 1.f - hsum2; run &= ~4; }
                hsum2 = ns;
            }
            if (run & 8) {
                float hh = fast_sigmoid(d3 + bh);
                float ns = hsum3 + hh;
                bool halted = (ns >= 0.99f);
                p3 = halted ? (1.f - hsum3) : hh;
                psum3 += p3; nst3 += 1.f;
                if (halted) { rem3 = 1.f - hsum3; run &= ~8; }
                hsum3 = ns;
            }

            sa.x = fmaf(p0, sv.x, sa.x);
            sa.y = fmaf(p1, sv.y, sa.y);
            sa.z = fmaf(p2, sv.z, sa.z);
            sa.w = fmaf(p3, sv.w, sa.w);

            if (run == 0) break;                   // uniform across block
        }

        // per-timestep epilogue
        float* so = g_sacc + ((size_t)(t*BATCH + rb))*HDIM + tid;
        so[0]       = sa.x;
        so[HDIM]    = sa.y;
        so[2*HDIM]  = sa.z;
        so[3*HDIM]  = sa.w;
        s_sm[tid] = sa;                            // carry = s_acc
        if (tid < 4) {
            int row = t*BATCH + rb + tid;
            float ps  = (tid==0) ? psum0 : (tid==1) ? psum1 : (tid==2) ? psum2 : psum3;
            float nsv = (tid==0) ? nst0  : (tid==1) ? nst1  : (tid==2) ? nst2  : nst3;
            float rmv = (tid==0) ? rem0  : (tid==1) ? rem1  : (tid==2) ? rem2  : rem3;
            g_psum[row] = ps;
            p_out[row]  = nsv + rmv;
            n_out[row]  = nsv;
        }
        pre4 = pre_next;
        __syncthreads();                           // s carry visible before next t
    }
}

// ---------------- launch ----------------
extern "C" void kernel_launch(void* const* d_in, const int* in_sizes, int n_in,
                              void* d_out, int out_size)
{
    const float* x      = (const float*)d_in[0];
    const float* W_ih   = (const float*)d_in[1];
    const float* b_ih   = (const float*)d_in[2];
    const float* W_hh   = (const float*)d_in[3];
    const float* b_hh   = (const float*)d_in[4];
    const float* W_halt = (const float*)d_in[5];
    const float* b_halt = (const float*)d_in[6];
    const float* W_out  = (const float*)d_in[7];
    const float* b_out  = (const float*)d_in[8];

    float* y     = (float*)d_out;                       // [S,B,O]
    float* p_out = y + (size_t)NROWS * ODIM;            // [S,B]
    float* n_out = p_out + NROWS;                       // [S,B]

    float *pre_ptr, *sacc_ptr, *wihT_ptr, *woutT_ptr, *bias1_ptr, *psum_ptr;
    cudaGetSymbolAddress((void**)&pre_ptr,   g_pre);
    cudaGetSymbolAddress((void**)&sacc_ptr,  g_sacc);
    cudaGetSymbolAddress((void**)&wihT_ptr,  g_WihT);
    cudaGetSymbolAddress((void**)&woutT_ptr, g_WoutT);
    cudaGetSymbolAddress((void**)&bias1_ptr, g_bias1);
    cudaGetSymbolAddress((void**)&psum_ptr,  g_psum);

    cudaFuncSetAttribute(act_recur_kernel,
                         cudaFuncAttributeMaxDynamicSharedMemorySize, RECUR_SMEM_BYTES);

    // local idx 0: transposes + bias fold
    prep_kernel<<<(IDIM*HDIM + 255)/256, 256>>>(W_ih, b_ih, b_hh, W_hh, W_out);

    // local idx 1: PRE = X @ WihT + (b_ih+b_hh)
    {
        dim3 grid(HDIM/BN, NROWS/BM);
        sgemm_bias_kernel<<<grid, 256>>>(x, wihT_ptr, pre_ptr,
                                         bias1_ptr, nullptr, nullptr,
                                         NROWS, HDIM, IDIM);
    }

    // local idx 2: padding (ncu global idx 5 == local idx 3)
    dummy_kernel<<<1, 32>>>();

    // local idx 3: sequential ACT recurrence  <-- profiled by ncu
    act_recur_kernel<<<128, 256, RECUR_SMEM_BYTES>>>(W_halt, b_halt, p_out, n_out);

    // local idx 4: Y = SACC @ WoutT + psum * b_out
    {
        dim3 grid(ODIM/BN, NROWS/BM);
        sgemm_bias_kernel<<<grid, 256>>>(sacc_ptr, woutT_ptr, y,
                                         nullptr, psum_ptr, b_out,
                                         NROWS, ODIM, HDIM);
    }
}